// round 11
// baseline (speedup 1.0000x reference)
#include <cuda_runtime.h>

#define NN 50000
#define IC 512
#define OC 128
#define NE 1600000
#define NB 196   // scan blocks: 196*256 = 50176 >= NN

typedef unsigned long long ull;

// ---------------------------------------------------------------------------
// Scratch (static __device__ — no allocation in kernel_launch)
__device__ int   g_deg[NN];
__device__ int   g_off[NN + 1];   // CSR row offsets (by dst)
__device__ int   g_cur[NN];       // scatter cursors
__device__ int   g_csrc[NE];      // CSR column = src node per edge
__device__ float g_dis[NN];
__device__ int   g_bsum[NB];      // per-block degree sums
__device__ int   g_bscan[NB + 1]; // exclusive scan of block sums
__device__ float g_y[(size_t)NN * OC];          // x @ W_enc (UNSCALED)
__device__ float g_h[(size_t)(NN + 32) * OC];   // relu(dis*(gather) + b), padded

// k-pair weights, lane-contiguous layout: [kp][j][cg] of ull2.
__device__ ulonglong2 g_WpE[256 * 4 * 16];
__device__ ulonglong2 g_WpD[64 * 4 * 64];

__device__ __forceinline__ void fma2(ull& d, ull a, ull b) {
    asm("fma.rn.f32x2 %0, %1, %2, %0;" : "+l"(d) : "l"(a), "l"(b));
}
__device__ __forceinline__ float2 up2(ull a) {
    float2 r;
    asm("mov.b64 {%0, %1}, %2;" : "=f"(r.x), "=f"(r.y) : "l"(a));
    return r;
}

// ---------------------------------------------------------------------------
// K0: zero deg
__global__ void k_zero() {
    int i = blockIdx.x * blockDim.x + threadIdx.x;
    if (i < NN) g_deg[i] = 0;
}

// K1: dst-degree histogram
__global__ void k_deg(const int* __restrict__ ei) {
    int i = blockIdx.x * blockDim.x + threadIdx.x;
    if (i < NE) atomicAdd(&g_deg[ei[NE + i]], 1);
}

// Scan stage 1: per-block sums of 256 degrees
__global__ __launch_bounds__(256) void k_bsum() {
    __shared__ int ss[8];
    int i = blockIdx.x * 256 + threadIdx.x;
    int v = (i < NN) ? g_deg[i] : 0;
#pragma unroll
    for (int o = 16; o; o >>= 1) v += __shfl_xor_sync(0xffffffffu, v, o);
    if ((threadIdx.x & 31) == 0) ss[threadIdx.x >> 5] = v;
    __syncthreads();
    if (threadIdx.x == 0) {
        int s = 0;
#pragma unroll
        for (int w = 0; w < 8; w++) s += ss[w];
        g_bsum[blockIdx.x] = s;
    }
}

// Scan stage 2: one block exclusive-scans NB block sums
__global__ __launch_bounds__(256) void k_bscan() {
    __shared__ int sc[256];
    int t = threadIdx.x;
    int v = (t < NB) ? g_bsum[t] : 0;
    sc[t] = v;
    __syncthreads();
    for (int off = 1; off < 256; off <<= 1) {
        int u = (t >= off) ? sc[t - off] : 0;
        __syncthreads();
        sc[t] += u;
        __syncthreads();
    }
    if (t < NB) g_bscan[t] = sc[t] - v;   // exclusive
    if (t == NB - 1) g_bscan[NB] = sc[t];
}

// Scan stage 3: per-block scan of degrees + global base -> off/cur/dis
__global__ __launch_bounds__(256) void k_off() {
    __shared__ int sc[256];
    int t = threadIdx.x;
    int i = blockIdx.x * 256 + t;
    int d = (i < NN) ? g_deg[i] : 0;
    sc[t] = d;
    __syncthreads();
    for (int off = 1; off < 256; off <<= 1) {
        int u = (t >= off) ? sc[t - off] : 0;
        __syncthreads();
        sc[t] += u;
        __syncthreads();
    }
    if (i < NN) {
        int base = g_bscan[blockIdx.x] + sc[t] - d;  // exclusive
        g_off[i] = base;
        g_cur[i] = base;
        g_dis[i] = rsqrtf((float)(d + 1));
        if (i == NN - 1) g_off[NN] = base + d;
    }
}

// K3: scatter edges into CSR (order within a row is irrelevant for a sum)
__global__ void k_scatter(const int* __restrict__ ei) {
    int i = blockIdx.x * blockDim.x + threadIdx.x;
    if (i >= NE) return;
    int s = ei[i];
    int d = ei[NE + i];
    int p = atomicAdd(&g_cur[d], 1);
    g_csrc[p] = s;
}

// K_prep: build lane-contiguous k-pair weight layouts
__global__ void k_prep(const float* __restrict__ We, const float* __restrict__ Wd) {
    int i = blockIdx.x * blockDim.x + threadIdx.x;
    if (i < 256 * 4 * 16) {  // enc
        int kp = i >> 6, j = (i >> 4) & 3, cg = i & 15;
        int c = cg * 8 + 2 * j;
        float4 v;
        v.x = We[(2 * kp) * OC + c];
        v.y = We[(2 * kp + 1) * OC + c];
        v.z = We[(2 * kp) * OC + c + 1];
        v.w = We[(2 * kp + 1) * OC + c + 1];
        ((float4*)g_WpE)[i] = v;
    }
    if (i < 64 * 4 * 64) {  // dec
        int kp = i >> 8, j = (i >> 6) & 3, cg = i & 63;
        int c = cg * 8 + 2 * j;
        float4 v;
        v.x = Wd[(2 * kp) * IC + c];
        v.y = Wd[(2 * kp + 1) * IC + c];
        v.z = Wd[(2 * kp) * IC + c + 1];
        v.w = Wd[(2 * kp + 1) * IC + c + 1];
        ((float4*)g_WpD)[i] = v;
    }
}

// ---------------------------------------------------------------------------
// K4: y = x @ W_enc (UNSCALED) via packed f32x2 FMA, K-paired.
// 64 rows/block, 256 threads. No dependency on graph build -> overlappable.
__global__ __launch_bounds__(256) void k_gemm1(const float* __restrict__ x) {
    const int tid = threadIdx.x;
    const int warp = tid >> 5, lane = tid & 31;
    const int cg = lane & 15, rg = lane >> 4;
    const int row0 = blockIdx.x * 64 + warp * 8 + rg * 4;

    const ulonglong2* __restrict__ xq = (const ulonglong2*)x;

    int r[4];
#pragma unroll
    for (int m = 0; m < 4; m++) r[m] = min(row0 + m, NN - 1);

    ull acc[4][8];
#pragma unroll
    for (int m = 0; m < 4; m++)
#pragma unroll
        for (int j = 0; j < 8; j++) acc[m][j] = 0ull;

    for (int kp = 0; kp < 256; kp += 4) {
        ulonglong2 xv[4][2];
#pragma unroll
        for (int m = 0; m < 4; m++) {
            size_t base = (size_t)r[m] * 128 + (kp >> 1);
            xv[m][0] = xq[base];
            xv[m][1] = xq[base + 1];
        }
#pragma unroll
        for (int kp2 = 0; kp2 < 4; kp2++) {
            const ulonglong2* wbase = &g_WpE[(kp + kp2) * 64 + cg];
            ulonglong2 w0 = wbase[0];
            ulonglong2 w1 = wbase[16];
            ulonglong2 w2 = wbase[32];
            ulonglong2 w3 = wbase[48];
#pragma unroll
            for (int m = 0; m < 4; m++) {
                ull xm = (kp2 & 1) ? xv[m][kp2 >> 1].y : xv[m][kp2 >> 1].x;
                fma2(acc[m][0], xm, w0.x);
                fma2(acc[m][1], xm, w0.y);
                fma2(acc[m][2], xm, w1.x);
                fma2(acc[m][3], xm, w1.y);
                fma2(acc[m][4], xm, w2.x);
                fma2(acc[m][5], xm, w2.y);
                fma2(acc[m][6], xm, w3.x);
                fma2(acc[m][7], xm, w3.y);
            }
        }
    }

#pragma unroll
    for (int m = 0; m < 4; m++) {
        int row = row0 + m;
        if (row >= NN) continue;
        float v[8];
#pragma unroll
        for (int j = 0; j < 8; j++) {
            float2 p = up2(acc[m][j]);
            v[j] = p.x + p.y;
        }
        float4* o = (float4*)(g_y + (size_t)row * OC + cg * 8);
        o[0] = make_float4(v[0], v[1], v[2], v[3]);
        o[1] = make_float4(v[4], v[5], v[6], v[7]);
    }
}

// ---------------------------------------------------------------------------
// K5: gather + epilogue for node range [n0c, n0c+cnt), one warp per node.
// h[n] = relu(dis[n]*(y[n]*dis[n] + sum_{src} y[src]*dis[src]) + b)
__global__ __launch_bounds__(256) void k_gather(const float* __restrict__ b,
                                                int n0c, int cnt) {
    const int w = blockIdx.x * 8 + (threadIdx.x >> 5);
    if (w >= cnt) return;
    const int lane = threadIdx.x & 31;
    const int n = n0c + w;

    const float4* __restrict__ y4 = (const float4*)g_y;

    float dn = g_dis[n];
    float4 a = y4[(size_t)n * 32 + lane];  // self loop: y[n] * dis[n]
    a.x *= dn; a.y *= dn; a.z *= dn; a.w *= dn;

    int e = g_off[n], end = g_off[n + 1];
    for (; e + 4 <= end; e += 4) {
        int s0 = g_csrc[e],     s1 = g_csrc[e + 1];
        int s2 = g_csrc[e + 2], s3 = g_csrc[e + 3];
        float d0 = g_dis[s0], d1 = g_dis[s1];
        float d2 = g_dis[s2], d3 = g_dis[s3];
        float4 v0 = y4[(size_t)s0 * 32 + lane];
        float4 v1 = y4[(size_t)s1 * 32 + lane];
        float4 v2 = y4[(size_t)s2 * 32 + lane];
        float4 v3 = y4[(size_t)s3 * 32 + lane];
        a.x = fmaf(v0.x, d0, a.x); a.y = fmaf(v0.y, d0, a.y);
        a.z = fmaf(v0.z, d0, a.z); a.w = fmaf(v0.w, d0, a.w);
        a.x = fmaf(v1.x, d1, a.x); a.y = fmaf(v1.y, d1, a.y);
        a.z = fmaf(v1.z, d1, a.z); a.w = fmaf(v1.w, d1, a.w);
        a.x = fmaf(v2.x, d2, a.x); a.y = fmaf(v2.y, d2, a.y);
        a.z = fmaf(v2.z, d2, a.z); a.w = fmaf(v2.w, d2, a.w);
        a.x = fmaf(v3.x, d3, a.x); a.y = fmaf(v3.y, d3, a.y);
        a.z = fmaf(v3.z, d3, a.z); a.w = fmaf(v3.w, d3, a.w);
    }
    for (; e < end; e++) {
        int s = g_csrc[e];
        float ds = g_dis[s];
        float4 v = y4[(size_t)s * 32 + lane];
        a.x = fmaf(v.x, ds, a.x); a.y = fmaf(v.y, ds, a.y);
        a.z = fmaf(v.z, ds, a.z); a.w = fmaf(v.w, ds, a.w);
    }
    const float4 b4 = ((const float4*)b)[lane];
    float4 h;
    h.x = fmaxf(fmaf(dn, a.x, b4.x), 0.f);
    h.y = fmaxf(fmaf(dn, a.y, b4.y), 0.f);
    h.z = fmaxf(fmaf(dn, a.z, b4.z), 0.f);
    h.w = fmaxf(fmaf(dn, a.w, b4.w), 0.f);
    ((float4*)g_h)[(size_t)n * 32 + lane] = h;
}

// ---------------------------------------------------------------------------
// K6: decode GEMM (f32x2, K-paired) + softmax from precomputed h.
// 16 nodes/block, 256 threads, node offset n0c.
__global__ __launch_bounds__(256) void k_dec(float* __restrict__ out, int n0c) {
    __shared__ __align__(16) float hs[16 * OC];  // 8 KB
    __shared__ float red[8][4];
    const int tid = threadIdx.x;
    const int warp = tid >> 5, lane = tid & 31;
    const int n0 = n0c + blockIdx.x * 16;
    const int cg = tid & 63, rg = tid >> 6;

    // coalesced tile load: 512 float4 by 256 threads
    const float4* __restrict__ h4 = (const float4*)(g_h + (size_t)n0 * OC);
    float4* hs4 = (float4*)hs;
    hs4[tid] = h4[tid];
    hs4[tid + 256] = h4[tid + 256];
    __syncthreads();

    const ulonglong2* hq = (const ulonglong2*)hs;  // 32 per node

    ull acc[4][8];
#pragma unroll
    for (int m = 0; m < 4; m++)
#pragma unroll
        for (int j = 0; j < 8; j++) acc[m][j] = 0ull;

    for (int kp = 0; kp < 64; kp += 4) {  // k step 8 over OC=128
        ulonglong2 hv[4][2];
#pragma unroll
        for (int m = 0; m < 4; m++) {
            int base = (rg * 4 + m) * 32 + (kp >> 1);
            hv[m][0] = hq[base];
            hv[m][1] = hq[base + 1];
        }
#pragma unroll
        for (int kp2 = 0; kp2 < 4; kp2++) {
            const ulonglong2* wbase = &g_WpD[(kp + kp2) * 256 + cg];
            ulonglong2 w0 = wbase[0];
            ulonglong2 w1 = wbase[64];
            ulonglong2 w2 = wbase[128];
            ulonglong2 w3 = wbase[192];
#pragma unroll
            for (int m = 0; m < 4; m++) {
                ull xm = (kp2 & 1) ? hv[m][kp2 >> 1].y : hv[m][kp2 >> 1].x;
                fma2(acc[m][0], xm, w0.x);
                fma2(acc[m][1], xm, w0.y);
                fma2(acc[m][2], xm, w1.x);
                fma2(acc[m][3], xm, w1.y);
                fma2(acc[m][4], xm, w2.x);
                fma2(acc[m][5], xm, w2.y);
                fma2(acc[m][6], xm, w3.x);
                fma2(acc[m][7], xm, w3.y);
            }
        }
    }

    float v[4][8];
#pragma unroll
    for (int m = 0; m < 4; m++) {
#pragma unroll
        for (int j = 0; j < 8; j++) {
            float2 p = up2(acc[m][j]);
            v[m][j] = p.x + p.y;
        }
    }

    // softmax: node (rg*4+m)'s 512 cols live in warps rg*2 and rg*2+1
#pragma unroll
    for (int m = 0; m < 4; m++) {
        float lm = v[m][0];
#pragma unroll
        for (int j = 1; j < 8; j++) lm = fmaxf(lm, v[m][j]);
#pragma unroll
        for (int o = 16; o; o >>= 1)
            lm = fmaxf(lm, __shfl_xor_sync(0xffffffffu, lm, o));
        if (lane == 0) red[warp][m] = lm;
    }
    __syncthreads();
    float rm[4];
#pragma unroll
    for (int m = 0; m < 4; m++)
        rm[m] = fmaxf(red[rg * 2][m], red[rg * 2 + 1][m]);
    __syncthreads();

#pragma unroll
    for (int m = 0; m < 4; m++) {
        float ls = 0.f;
#pragma unroll
        for (int j = 0; j < 8; j++) {
            v[m][j] = __expf(v[m][j] - rm[m]);
            ls += v[m][j];
        }
#pragma unroll
        for (int o = 16; o; o >>= 1)
            ls += __shfl_xor_sync(0xffffffffu, ls, o);
        if (lane == 0) red[warp][m] = ls;
    }
    __syncthreads();

#pragma unroll
    for (int m = 0; m < 4; m++) {
        float inv = 1.f / (red[rg * 2][m] + red[rg * 2 + 1][m]);
        int row = n0 + rg * 4 + m;
        float4* o = (float4*)(out + (size_t)row * IC + cg * 8);
        o[0] = make_float4(v[m][0] * inv, v[m][1] * inv, v[m][2] * inv, v[m][3] * inv);
        o[1] = make_float4(v[m][4] * inv, v[m][5] * inv, v[m][6] * inv, v[m][7] * inv);
    }
}

// ---------------------------------------------------------------------------
extern "C" void kernel_launch(void* const* d_in, const int* in_sizes, int n_in,
                              void* d_out, int out_size) {
    const float* x    = (const float*)d_in[0];
    const int*   ei   = (const int*)d_in[1];
    const float* Wenc = (const float*)d_in[2];
    const float* benc = (const float*)d_in[3];
    const float* Wdec = (const float*)d_in[4];
    float*       out  = (float*)d_out;

    // Streams/events created once on first (non-capture) call; reused.
    static cudaStream_t sB = nullptr;
    static cudaEvent_t evF = nullptr, evM = nullptr, evG[4] = {};
    if (sB == nullptr) {
        cudaStreamCreateWithFlags(&sB, cudaStreamNonBlocking);
        cudaEventCreateWithFlags(&evF, cudaEventDisableTiming);
        cudaEventCreateWithFlags(&evM, cudaEventDisableTiming);
        for (int i = 0; i < 4; i++)
            cudaEventCreateWithFlags(&evG[i], cudaEventDisableTiming);
    }

    // fork: stream B builds the CSR while the main stream runs the encode GEMM
    cudaEventRecord(evF, 0);
    cudaStreamWaitEvent(sB, evF, 0);

    k_zero<<<(NN + 255) / 256, 256, 0, sB>>>();
    k_deg<<<(NE + 255) / 256, 256, 0, sB>>>(ei);
    k_bsum<<<NB, 256, 0, sB>>>();
    k_bscan<<<1, 256, 0, sB>>>();
    k_off<<<NB, 256, 0, sB>>>();
    k_scatter<<<(NE + 255) / 256, 256, 0, sB>>>(ei);

    k_prep<<<64, 256>>>(Wenc, Wdec);
    k_gemm1<<<(NN + 63) / 64, 256>>>(x);
    cudaEventRecord(evM, 0);           // gemm1 done (gather needs full g_y)
    cudaStreamWaitEvent(sB, evM, 0);   // sB now has CSR + g_y

    // pipelined tail: gather chunk i on sB, dec chunk i on main after evG[i]
    const int blkc[4] = {782, 781, 781, 781};  // dec blocks per chunk (sum 3125)
    int n0c = 0;
    for (int i = 0; i < 4; i++) {
        int cnt = blkc[i] * 16;
        k_gather<<<(cnt + 7) / 8, 256, 0, sB>>>(benc, n0c, cnt);
        cudaEventRecord(evG[i], sB);
        cudaStreamWaitEvent(0, evG[i], 0);
        k_dec<<<blkc[i], 256>>>(out, n0c);
        n0c += cnt;
    }
}

// round 12
// speedup vs baseline: 1.3109x; 1.3109x over previous
#include <cuda_runtime.h>

#define NN 50000
#define IC 512
#define OC 128
#define NE 1600000
#define NB 196   // scan blocks: 196*256 = 50176 >= NN

typedef unsigned long long ull;
typedef unsigned int uint;

// ---------------------------------------------------------------------------
// Scratch (static __device__ — no allocation in kernel_launch)
__device__ int   g_deg[NN];
__device__ int   g_off[NN + 1];   // CSR row offsets (by dst)
__device__ int   g_cur[NN];       // scatter cursors
__device__ int   g_csrc[NE];      // CSR column = src node per edge
__device__ float g_dis[NN];
__device__ int   g_bsum[NB];      // per-block degree sums
__device__ int   g_bscan[NB + 1]; // exclusive scan of block sums
__device__ float g_y[(size_t)NN * OC];          // x @ W_enc (UNSCALED)
__device__ float g_h[(size_t)(NN + 32) * OC];   // relu(dis*(gather) + b), padded

// enc k-pair weights, lane-contiguous (validated f32x2 path)
__device__ ulonglong2 g_WpE[256 * 4 * 16];
// dec tf32 B fragments: [kt(16)][gnt(64)][lane(32)] of uint2 (b0,b1), tf32 bits
__device__ uint2 g_BpD[16 * 64 * 32];

__device__ __forceinline__ void fma2(ull& d, ull a, ull b) {
    asm("fma.rn.f32x2 %0, %1, %2, %0;" : "+l"(d) : "l"(a), "l"(b));
}
__device__ __forceinline__ float2 up2(ull a) {
    float2 r;
    asm("mov.b64 {%0, %1}, %2;" : "=f"(r.x), "=f"(r.y) : "l"(a));
    return r;
}
__device__ __forceinline__ uint tf32c(float f) {
    uint u;
    asm("cvt.rna.tf32.f32 %0, %1;" : "=r"(u) : "f"(f));
    return u;
}

// ---------------------------------------------------------------------------
// K0: zero deg
__global__ void k_zero() {
    int i = blockIdx.x * blockDim.x + threadIdx.x;
    if (i < NN) g_deg[i] = 0;
}

// K1: dst-degree histogram
__global__ void k_deg(const int* __restrict__ ei) {
    int i = blockIdx.x * blockDim.x + threadIdx.x;
    if (i < NE) atomicAdd(&g_deg[ei[NE + i]], 1);
}

// Scan stage 1: per-block sums of 256 degrees
__global__ __launch_bounds__(256) void k_bsum() {
    __shared__ int ss[8];
    int i = blockIdx.x * 256 + threadIdx.x;
    int v = (i < NN) ? g_deg[i] : 0;
#pragma unroll
    for (int o = 16; o; o >>= 1) v += __shfl_xor_sync(0xffffffffu, v, o);
    if ((threadIdx.x & 31) == 0) ss[threadIdx.x >> 5] = v;
    __syncthreads();
    if (threadIdx.x == 0) {
        int s = 0;
#pragma unroll
        for (int w = 0; w < 8; w++) s += ss[w];
        g_bsum[blockIdx.x] = s;
    }
}

// Scan stage 2: one block exclusive-scans NB block sums
__global__ __launch_bounds__(256) void k_bscan() {
    __shared__ int sc[256];
    int t = threadIdx.x;
    int v = (t < NB) ? g_bsum[t] : 0;
    sc[t] = v;
    __syncthreads();
    for (int off = 1; off < 256; off <<= 1) {
        int u = (t >= off) ? sc[t - off] : 0;
        __syncthreads();
        sc[t] += u;
        __syncthreads();
    }
    if (t < NB) g_bscan[t] = sc[t] - v;   // exclusive
    if (t == NB - 1) g_bscan[NB] = sc[t];
}

// Scan stage 3: per-block scan of degrees + global base -> off/cur/dis
__global__ __launch_bounds__(256) void k_off() {
    __shared__ int sc[256];
    int t = threadIdx.x;
    int i = blockIdx.x * 256 + t;
    int d = (i < NN) ? g_deg[i] : 0;
    sc[t] = d;
    __syncthreads();
    for (int off = 1; off < 256; off <<= 1) {
        int u = (t >= off) ? sc[t - off] : 0;
        __syncthreads();
        sc[t] += u;
        __syncthreads();
    }
    if (i < NN) {
        int base = g_bscan[blockIdx.x] + sc[t] - d;  // exclusive
        g_off[i] = base;
        g_cur[i] = base;
        g_dis[i] = rsqrtf((float)(d + 1));
        if (i == NN - 1) g_off[NN] = base + d;
    }
}

// K3: scatter edges into CSR (order within a row is irrelevant for a sum)
__global__ void k_scatter(const int* __restrict__ ei) {
    int i = blockIdx.x * blockDim.x + threadIdx.x;
    if (i >= NE) return;
    int s = ei[i];
    int d = ei[NE + i];
    int p = atomicAdd(&g_cur[d], 1);
    g_csrc[p] = s;
}

// K_prep: enc k-pair layout + dec tf32 B fragments
__global__ void k_prep(const float* __restrict__ We, const float* __restrict__ Wd) {
    int i = blockIdx.x * blockDim.x + threadIdx.x;
    if (i < 256 * 4 * 16) {  // enc
        int kp = i >> 6, j = (i >> 4) & 3, cg = i & 15;
        int c = cg * 8 + 2 * j;
        float4 v;
        v.x = We[(2 * kp) * OC + c];
        v.y = We[(2 * kp + 1) * OC + c];
        v.z = We[(2 * kp) * OC + c + 1];
        v.w = We[(2 * kp + 1) * OC + c + 1];
        ((float4*)g_WpE)[i] = v;
    }
    if (i < 16 * 64 * 32) {  // dec B fragments (m16n8k8 tf32, row.col)
        int kt = i >> 11, gnt = (i >> 5) & 63, lane = i & 31;
        int k = kt * 8 + (lane & 3);
        int n = gnt * 8 + (lane >> 2);
        uint2 b;
        b.x = tf32c(Wd[k * IC + n]);
        b.y = tf32c(Wd[(k + 4) * IC + n]);
        g_BpD[i] = b;
    }
}

// ---------------------------------------------------------------------------
// K4: y = x @ W_enc (UNSCALED) via packed f32x2 FMA, K-paired.
// 64 rows/block, 256 threads. No dependency on graph build -> overlappable.
__global__ __launch_bounds__(256) void k_gemm1(const float* __restrict__ x) {
    const int tid = threadIdx.x;
    const int warp = tid >> 5, lane = tid & 31;
    const int cg = lane & 15, rg = lane >> 4;
    const int row0 = blockIdx.x * 64 + warp * 8 + rg * 4;

    const ulonglong2* __restrict__ xq = (const ulonglong2*)x;

    int r[4];
#pragma unroll
    for (int m = 0; m < 4; m++) r[m] = min(row0 + m, NN - 1);

    ull acc[4][8];
#pragma unroll
    for (int m = 0; m < 4; m++)
#pragma unroll
        for (int j = 0; j < 8; j++) acc[m][j] = 0ull;

    for (int kp = 0; kp < 256; kp += 4) {
        ulonglong2 xv[4][2];
#pragma unroll
        for (int m = 0; m < 4; m++) {
            size_t base = (size_t)r[m] * 128 + (kp >> 1);
            xv[m][0] = xq[base];
            xv[m][1] = xq[base + 1];
        }
#pragma unroll
        for (int kp2 = 0; kp2 < 4; kp2++) {
            const ulonglong2* wbase = &g_WpE[(kp + kp2) * 64 + cg];
            ulonglong2 w0 = wbase[0];
            ulonglong2 w1 = wbase[16];
            ulonglong2 w2 = wbase[32];
            ulonglong2 w3 = wbase[48];
#pragma unroll
            for (int m = 0; m < 4; m++) {
                ull xm = (kp2 & 1) ? xv[m][kp2 >> 1].y : xv[m][kp2 >> 1].x;
                fma2(acc[m][0], xm, w0.x);
                fma2(acc[m][1], xm, w0.y);
                fma2(acc[m][2], xm, w1.x);
                fma2(acc[m][3], xm, w1.y);
                fma2(acc[m][4], xm, w2.x);
                fma2(acc[m][5], xm, w2.y);
                fma2(acc[m][6], xm, w3.x);
                fma2(acc[m][7], xm, w3.y);
            }
        }
    }

#pragma unroll
    for (int m = 0; m < 4; m++) {
        int row = row0 + m;
        if (row >= NN) continue;
        float v[8];
#pragma unroll
        for (int j = 0; j < 8; j++) {
            float2 p = up2(acc[m][j]);
            v[j] = p.x + p.y;
        }
        float4* o = (float4*)(g_y + (size_t)row * OC + cg * 8);
        o[0] = make_float4(v[0], v[1], v[2], v[3]);
        o[1] = make_float4(v[4], v[5], v[6], v[7]);
    }
}

// ---------------------------------------------------------------------------
// K5: gather + epilogue, one warp per node, high occupancy.
// h[n] = relu(dis[n]*(y[n]*dis[n] + sum_{src} y[src]*dis[src]) + b)
__global__ __launch_bounds__(256) void k_gather(const float* __restrict__ b) {
    const int w = blockIdx.x * 8 + (threadIdx.x >> 5);
    if (w >= NN) return;
    const int lane = threadIdx.x & 31;
    const int n = w;

    const float4* __restrict__ y4 = (const float4*)g_y;

    float dn = g_dis[n];
    float4 a = y4[(size_t)n * 32 + lane];  // self loop: y[n] * dis[n]
    a.x *= dn; a.y *= dn; a.z *= dn; a.w *= dn;

    int e = g_off[n], end = g_off[n + 1];
    for (; e + 4 <= end; e += 4) {
        int s0 = g_csrc[e],     s1 = g_csrc[e + 1];
        int s2 = g_csrc[e + 2], s3 = g_csrc[e + 3];
        float d0 = g_dis[s0], d1 = g_dis[s1];
        float d2 = g_dis[s2], d3 = g_dis[s3];
        float4 v0 = y4[(size_t)s0 * 32 + lane];
        float4 v1 = y4[(size_t)s1 * 32 + lane];
        float4 v2 = y4[(size_t)s2 * 32 + lane];
        float4 v3 = y4[(size_t)s3 * 32 + lane];
        a.x = fmaf(v0.x, d0, a.x); a.y = fmaf(v0.y, d0, a.y);
        a.z = fmaf(v0.z, d0, a.z); a.w = fmaf(v0.w, d0, a.w);
        a.x = fmaf(v1.x, d1, a.x); a.y = fmaf(v1.y, d1, a.y);
        a.z = fmaf(v1.z, d1, a.z); a.w = fmaf(v1.w, d1, a.w);
        a.x = fmaf(v2.x, d2, a.x); a.y = fmaf(v2.y, d2, a.y);
        a.z = fmaf(v2.z, d2, a.z); a.w = fmaf(v2.w, d2, a.w);
        a.x = fmaf(v3.x, d3, a.x); a.y = fmaf(v3.y, d3, a.y);
        a.z = fmaf(v3.z, d3, a.z); a.w = fmaf(v3.w, d3, a.w);
    }
    for (; e < end; e++) {
        int s = g_csrc[e];
        float ds = g_dis[s];
        float4 v = y4[(size_t)s * 32 + lane];
        a.x = fmaf(v.x, ds, a.x); a.y = fmaf(v.y, ds, a.y);
        a.z = fmaf(v.z, ds, a.z); a.w = fmaf(v.w, ds, a.w);
    }
    const float4 b4 = ((const float4*)b)[lane];
    float4 h;
    h.x = fmaxf(fmaf(dn, a.x, b4.x), 0.f);
    h.y = fmaxf(fmaf(dn, a.y, b4.y), 0.f);
    h.z = fmaxf(fmaf(dn, a.z, b4.z), 0.f);
    h.w = fmaxf(fmaf(dn, a.w, b4.w), 0.f);
    ((float4*)g_h)[(size_t)n * 32 + lane] = h;
}

// ---------------------------------------------------------------------------
// K6: decode GEMM via tf32 mma.sync m16n8k8 + softmax.
// 32 nodes/block (two m16 A-tiles), 256 threads (8 warps).
// Warp w owns output cols [w*64, w*64+64) = 8 n-tiles of 8.
__global__ __launch_bounds__(256) void k_dec(float* __restrict__ out) {
    __shared__ __align__(16) float hs[32 * 132];   // row stride 132: conflict-free A LDS
    __shared__ float red_m[2][16][8];
    __shared__ float red_s[2][16][8];
    const int tid = threadIdx.x, warp = tid >> 5, lane = tid & 31;
    const int q = lane >> 2, c2 = lane & 3;
    const int n0 = blockIdx.x * 32;

    // load 32 h-rows (128 floats) into hs (g_h is padded past NN; pad rows are 0)
#pragma unroll
    for (int it = 0; it < 4; it++) {
        int idx = it * 256 + tid;          // 0..1023
        int row = idx >> 5, c4 = idx & 31;
        float4 v = *(const float4*)(g_h + (size_t)(n0 + row) * OC + c4 * 4);
        *(float4*)&hs[row * 132 + c4 * 4] = v;
    }
    __syncthreads();

    float c[2][8][4];
#pragma unroll
    for (int t = 0; t < 2; t++)
#pragma unroll
        for (int nt = 0; nt < 8; nt++)
#pragma unroll
            for (int j = 0; j < 4; j++) c[t][nt][j] = 0.f;

    for (int kt = 0; kt < 16; kt++) {
        uint a[2][4];
#pragma unroll
        for (int t = 0; t < 2; t++) {
            int r0 = t * 16 + q;
            a[t][0] = tf32c(hs[r0 * 132 + kt * 8 + c2]);
            a[t][1] = tf32c(hs[(r0 + 8) * 132 + kt * 8 + c2]);
            a[t][2] = tf32c(hs[r0 * 132 + kt * 8 + c2 + 4]);
            a[t][3] = tf32c(hs[(r0 + 8) * 132 + kt * 8 + c2 + 4]);
        }
#pragma unroll
        for (int nt = 0; nt < 8; nt++) {
            uint2 b = g_BpD[(kt * 64 + warp * 8 + nt) * 32 + lane];
#pragma unroll
            for (int t = 0; t < 2; t++) {
                asm volatile(
                    "mma.sync.aligned.m16n8k8.row.col.f32.tf32.tf32.f32 "
                    "{%0,%1,%2,%3}, {%4,%5,%6,%7}, {%8,%9}, {%0,%1,%2,%3};"
                    : "+f"(c[t][nt][0]), "+f"(c[t][nt][1]),
                      "+f"(c[t][nt][2]), "+f"(c[t][nt][3])
                    : "r"(a[t][0]), "r"(a[t][1]), "r"(a[t][2]), "r"(a[t][3]),
                      "r"(b.x), "r"(b.y));
            }
        }
    }

    // --- softmax over 512 cols per row ---
    // thread holds: rows (t*16+q): c[t][nt][0..1] at cols w*64+nt*8+2*c2, +1
    //               rows (t*16+q+8): c[t][nt][2..3] same cols
#pragma unroll
    for (int t = 0; t < 2; t++) {
        float mL = -1e30f, mH = -1e30f;
#pragma unroll
        for (int nt = 0; nt < 8; nt++) {
            mL = fmaxf(mL, fmaxf(c[t][nt][0], c[t][nt][1]));
            mH = fmaxf(mH, fmaxf(c[t][nt][2], c[t][nt][3]));
        }
        mL = fmaxf(mL, __shfl_xor_sync(0xffffffffu, mL, 1));
        mL = fmaxf(mL, __shfl_xor_sync(0xffffffffu, mL, 2));
        mH = fmaxf(mH, __shfl_xor_sync(0xffffffffu, mH, 1));
        mH = fmaxf(mH, __shfl_xor_sync(0xffffffffu, mH, 2));
        if (c2 == 0) {
            red_m[t][q][warp] = mL;
            red_m[t][q + 8][warp] = mH;
        }
    }
    __syncthreads();

    float inv[2][2];
#pragma unroll
    for (int t = 0; t < 2; t++) {
        float rmL = red_m[t][q][0], rmH = red_m[t][q + 8][0];
#pragma unroll
        for (int w2 = 1; w2 < 8; w2++) {
            rmL = fmaxf(rmL, red_m[t][q][w2]);
            rmH = fmaxf(rmH, red_m[t][q + 8][w2]);
        }
        float sL = 0.f, sH = 0.f;
#pragma unroll
        for (int nt = 0; nt < 8; nt++) {
            c[t][nt][0] = __expf(c[t][nt][0] - rmL);
            c[t][nt][1] = __expf(c[t][nt][1] - rmL);
            c[t][nt][2] = __expf(c[t][nt][2] - rmH);
            c[t][nt][3] = __expf(c[t][nt][3] - rmH);
            sL += c[t][nt][0] + c[t][nt][1];
            sH += c[t][nt][2] + c[t][nt][3];
        }
        sL += __shfl_xor_sync(0xffffffffu, sL, 1);
        sL += __shfl_xor_sync(0xffffffffu, sL, 2);
        sH += __shfl_xor_sync(0xffffffffu, sH, 1);
        sH += __shfl_xor_sync(0xffffffffu, sH, 2);
        if (c2 == 0) {
            red_s[t][q][warp] = sL;
            red_s[t][q + 8][warp] = sH;
        }
    }
    __syncthreads();

#pragma unroll
    for (int t = 0; t < 2; t++) {
        float sL = 0.f, sH = 0.f;
#pragma unroll
        for (int w2 = 0; w2 < 8; w2++) {
            sL += red_s[t][q][w2];
            sH += red_s[t][q + 8][w2];
        }
        inv[t][0] = 1.f / sL;
        inv[t][1] = 1.f / sH;
    }

#pragma unroll
    for (int t = 0; t < 2; t++) {
        int rowL = n0 + t * 16 + q;
        int rowH = rowL + 8;
#pragma unroll
        for (int nt = 0; nt < 8; nt++) {
            int col = warp * 64 + nt * 8 + 2 * c2;
            if (rowL < NN) {
                float2 v = make_float2(c[t][nt][0] * inv[t][0],
                                       c[t][nt][1] * inv[t][0]);
                *(float2*)&out[(size_t)rowL * IC + col] = v;
            }
            if (rowH < NN) {
                float2 v = make_float2(c[t][nt][2] * inv[t][1],
                                       c[t][nt][3] * inv[t][1]);
                *(float2*)&out[(size_t)rowH * IC + col] = v;
            }
        }
    }
}

// ---------------------------------------------------------------------------
extern "C" void kernel_launch(void* const* d_in, const int* in_sizes, int n_in,
                              void* d_out, int out_size) {
    const float* x    = (const float*)d_in[0];
    const int*   ei   = (const int*)d_in[1];
    const float* Wenc = (const float*)d_in[2];
    const float* benc = (const float*)d_in[3];
    const float* Wdec = (const float*)d_in[4];
    float*       out  = (float*)d_out;

    // Streams/events created once on first (non-capture) call; reused.
    static cudaStream_t sB = nullptr;
    static cudaEvent_t evF = nullptr, evJ = nullptr;
    if (sB == nullptr) {
        cudaStreamCreateWithFlags(&sB, cudaStreamNonBlocking);
        cudaEventCreateWithFlags(&evF, cudaEventDisableTiming);
        cudaEventCreateWithFlags(&evJ, cudaEventDisableTiming);
    }

    // fork: stream B builds the CSR while the main stream runs the encode GEMM
    cudaEventRecord(evF, 0);
    cudaStreamWaitEvent(sB, evF, 0);

    k_zero<<<(NN + 255) / 256, 256, 0, sB>>>();
    k_deg<<<(NE + 255) / 256, 256, 0, sB>>>(ei);
    k_bsum<<<NB, 256, 0, sB>>>();
    k_bscan<<<1, 256, 0, sB>>>();
    k_off<<<NB, 256, 0, sB>>>();
    k_scatter<<<(NE + 255) / 256, 256, 0, sB>>>(ei);

    k_prep<<<128, 256>>>(Wenc, Wdec);
    k_gemm1<<<(NN + 63) / 64, 256>>>(x);

    // join
    cudaEventRecord(evJ, sB);
    cudaStreamWaitEvent(0, evJ, 0);

    k_gather<<<(NN + 7) / 8, 256>>>(benc);
    k_dec<<<(NN + 31) / 32, 256>>>(out);
}

// round 13
// speedup vs baseline: 2.0512x; 1.5648x over previous
#include <cuda_runtime.h>

#define NN 50000
#define IC 512
#define OC 128
#define NE 1600000
#define NB 196   // scan blocks: 196*256 = 50176 >= NN

typedef unsigned long long ull;
typedef unsigned int uint;

// ---------------------------------------------------------------------------
// Scratch (static __device__ — no allocation in kernel_launch)
__device__ int   g_deg[NN];
__device__ int   g_off[NN + 1];   // CSR row offsets (by dst)
__device__ int   g_cur[NN];       // scatter cursors
__device__ int   g_csrc[NE];      // CSR column = src node per edge
__device__ float g_dis[NN];
__device__ int   g_bsum[NB];      // per-block degree sums
__device__ int   g_bscan[NB + 1]; // exclusive scan of block sums
__device__ float g_y[(size_t)NN * OC];          // x @ W_enc (UNSCALED)
__device__ float g_h[(size_t)(NN + 32) * OC];   // relu(dis*(gather) + b), padded

// tf32 B fragments, lane-contiguous:
// enc: [kt(64)][gnt(16)][lane(32)] uint2   (W_enc 512x128)
// dec: [kt(16)][gnt(64)][lane(32)] uint2   (W_dec 128x512)
__device__ uint2 g_BpE[64 * 16 * 32];
__device__ uint2 g_BpD[16 * 64 * 32];

__device__ __forceinline__ uint tf32c(float f) {
    uint u;
    asm("cvt.rna.tf32.f32 %0, %1;" : "=r"(u) : "f"(f));
    return u;
}
__device__ __forceinline__ void mma_tf32(float* c, const uint* a, uint2 b) {
    asm volatile(
        "mma.sync.aligned.m16n8k8.row.col.f32.tf32.tf32.f32 "
        "{%0,%1,%2,%3}, {%4,%5,%6,%7}, {%8,%9}, {%0,%1,%2,%3};"
        : "+f"(c[0]), "+f"(c[1]), "+f"(c[2]), "+f"(c[3])
        : "r"(a[0]), "r"(a[1]), "r"(a[2]), "r"(a[3]), "r"(b.x), "r"(b.y));
}

// ---------------------------------------------------------------------------
// K0: zero deg
__global__ void k_zero() {
    int i = blockIdx.x * blockDim.x + threadIdx.x;
    if (i < NN) g_deg[i] = 0;
}

// K1: dst-degree histogram
__global__ void k_deg(const int* __restrict__ ei) {
    int i = blockIdx.x * blockDim.x + threadIdx.x;
    if (i < NE) atomicAdd(&g_deg[ei[NE + i]], 1);
}

// Scan stage 1: per-block sums of 256 degrees
__global__ __launch_bounds__(256) void k_bsum() {
    __shared__ int ss[8];
    int i = blockIdx.x * 256 + threadIdx.x;
    int v = (i < NN) ? g_deg[i] : 0;
#pragma unroll
    for (int o = 16; o; o >>= 1) v += __shfl_xor_sync(0xffffffffu, v, o);
    if ((threadIdx.x & 31) == 0) ss[threadIdx.x >> 5] = v;
    __syncthreads();
    if (threadIdx.x == 0) {
        int s = 0;
#pragma unroll
        for (int w = 0; w < 8; w++) s += ss[w];
        g_bsum[blockIdx.x] = s;
    }
}

// Scan stage 2: one block exclusive-scans NB block sums
__global__ __launch_bounds__(256) void k_bscan() {
    __shared__ int sc[256];
    int t = threadIdx.x;
    int v = (t < NB) ? g_bsum[t] : 0;
    sc[t] = v;
    __syncthreads();
    for (int off = 1; off < 256; off <<= 1) {
        int u = (t >= off) ? sc[t - off] : 0;
        __syncthreads();
        sc[t] += u;
        __syncthreads();
    }
    if (t < NB) g_bscan[t] = sc[t] - v;   // exclusive
    if (t == NB - 1) g_bscan[NB] = sc[t];
}

// Scan stage 3: per-block scan of degrees + global base -> off/cur/dis
__global__ __launch_bounds__(256) void k_off() {
    __shared__ int sc[256];
    int t = threadIdx.x;
    int i = blockIdx.x * 256 + t;
    int d = (i < NN) ? g_deg[i] : 0;
    sc[t] = d;
    __syncthreads();
    for (int off = 1; off < 256; off <<= 1) {
        int u = (t >= off) ? sc[t - off] : 0;
        __syncthreads();
        sc[t] += u;
        __syncthreads();
    }
    if (i < NN) {
        int base = g_bscan[blockIdx.x] + sc[t] - d;  // exclusive
        g_off[i] = base;
        g_cur[i] = base;
        g_dis[i] = rsqrtf((float)(d + 1));
        if (i == NN - 1) g_off[NN] = base + d;
    }
}

// K3: scatter edges into CSR (order within a row is irrelevant for a sum)
__global__ void k_scatter(const int* __restrict__ ei) {
    int i = blockIdx.x * blockDim.x + threadIdx.x;
    if (i >= NE) return;
    int s = ei[i];
    int d = ei[NE + i];
    int p = atomicAdd(&g_cur[d], 1);
    g_csrc[p] = s;
}

// K_prep: tf32 B fragments for both GEMMs (each 32768 threads' worth)
__global__ void k_prep(const float* __restrict__ We, const float* __restrict__ Wd) {
    int i = blockIdx.x * blockDim.x + threadIdx.x;
    if (i < 64 * 16 * 32) {  // enc fragments
        int kt = i >> 9, gnt = (i >> 5) & 15, lane = i & 31;
        int k = kt * 8 + (lane & 3);
        int n = gnt * 8 + (lane >> 2);
        uint2 b;
        b.x = tf32c(We[k * OC + n]);
        b.y = tf32c(We[(k + 4) * OC + n]);
        g_BpE[i] = b;
    }
    if (i < 16 * 64 * 32) {  // dec fragments
        int kt = i >> 11, gnt = (i >> 5) & 63, lane = i & 31;
        int k = kt * 8 + (lane & 3);
        int n = gnt * 8 + (lane >> 2);
        uint2 b;
        b.x = tf32c(Wd[k * IC + n]);
        b.y = tf32c(Wd[(k + 4) * IC + n]);
        g_BpD[i] = b;
    }
}

// ---------------------------------------------------------------------------
// K4: y = x @ W_enc (UNSCALED) via tf32 mma m16n8k8.
// 32 rows/block (two m16 tiles), 256 threads (8 warps), warp owns 16 cols.
// K=512 staged through smem in four 32x128 chunks.
__global__ __launch_bounds__(256) void k_gemm1(const float* __restrict__ x) {
    __shared__ __align__(16) float xs[32 * 132];  // row stride 132
    const int tid = threadIdx.x, warp = tid >> 5, lane = tid & 31;
    const int q = lane >> 2, c2 = lane & 3;
    const int r0blk = blockIdx.x * 32;

    float c[2][2][4];
#pragma unroll
    for (int t = 0; t < 2; t++)
#pragma unroll
        for (int nt = 0; nt < 2; nt++)
#pragma unroll
            for (int j = 0; j < 4; j++) c[t][nt][j] = 0.f;

#pragma unroll 1
    for (int ch = 0; ch < 4; ch++) {
        __syncthreads();
        // load 32 rows x 128 K-cols: 1024 float4 by 256 threads
#pragma unroll
        for (int it = 0; it < 4; it++) {
            int idx = it * 256 + tid;
            int row = idx >> 5, c4 = idx & 31;
            int grow = min(r0blk + row, NN - 1);
            float4 v = *(const float4*)(x + (size_t)grow * IC + ch * 128 + c4 * 4);
            *(float4*)&xs[row * 132 + c4 * 4] = v;
        }
        __syncthreads();

#pragma unroll
        for (int kt2 = 0; kt2 < 16; kt2++) {
            int ktg = ch * 16 + kt2;
            uint a[2][4];
#pragma unroll
            for (int t = 0; t < 2; t++) {
                int r = t * 16 + q;
                a[t][0] = tf32c(xs[r * 132 + kt2 * 8 + c2]);
                a[t][1] = tf32c(xs[(r + 8) * 132 + kt2 * 8 + c2]);
                a[t][2] = tf32c(xs[r * 132 + kt2 * 8 + c2 + 4]);
                a[t][3] = tf32c(xs[(r + 8) * 132 + kt2 * 8 + c2 + 4]);
            }
#pragma unroll
            for (int nt = 0; nt < 2; nt++) {
                uint2 b = g_BpE[(ktg * 16 + warp * 2 + nt) * 32 + lane];
#pragma unroll
                for (int t = 0; t < 2; t++) mma_tf32(c[t][nt], a[t], b);
            }
        }
    }

    // write y (unscaled)
#pragma unroll
    for (int t = 0; t < 2; t++) {
        int rowL = r0blk + t * 16 + q;
        int rowH = rowL + 8;
#pragma unroll
        for (int nt = 0; nt < 2; nt++) {
            int col = warp * 16 + nt * 8 + 2 * c2;
            if (rowL < NN)
                *(float2*)&g_y[(size_t)rowL * OC + col] =
                    make_float2(c[t][nt][0], c[t][nt][1]);
            if (rowH < NN)
                *(float2*)&g_y[(size_t)rowH * OC + col] =
                    make_float2(c[t][nt][2], c[t][nt][3]);
        }
    }
}

// ---------------------------------------------------------------------------
// K5: gather + epilogue, one warp per node, high occupancy.
// h[n] = relu(dis[n]*(y[n]*dis[n] + sum_{src} y[src]*dis[src]) + b)
__global__ __launch_bounds__(256) void k_gather(const float* __restrict__ b) {
    const int w = blockIdx.x * 8 + (threadIdx.x >> 5);
    if (w >= NN) return;
    const int lane = threadIdx.x & 31;
    const int n = w;

    const float4* __restrict__ y4 = (const float4*)g_y;

    float dn = g_dis[n];
    float4 a = y4[(size_t)n * 32 + lane];  // self loop: y[n] * dis[n]
    a.x *= dn; a.y *= dn; a.z *= dn; a.w *= dn;

    int e = g_off[n], end = g_off[n + 1];
    for (; e + 4 <= end; e += 4) {
        int s0 = g_csrc[e],     s1 = g_csrc[e + 1];
        int s2 = g_csrc[e + 2], s3 = g_csrc[e + 3];
        float d0 = g_dis[s0], d1 = g_dis[s1];
        float d2 = g_dis[s2], d3 = g_dis[s3];
        float4 v0 = y4[(size_t)s0 * 32 + lane];
        float4 v1 = y4[(size_t)s1 * 32 + lane];
        float4 v2 = y4[(size_t)s2 * 32 + lane];
        float4 v3 = y4[(size_t)s3 * 32 + lane];
        a.x = fmaf(v0.x, d0, a.x); a.y = fmaf(v0.y, d0, a.y);
        a.z = fmaf(v0.z, d0, a.z); a.w = fmaf(v0.w, d0, a.w);
        a.x = fmaf(v1.x, d1, a.x); a.y = fmaf(v1.y, d1, a.y);
        a.z = fmaf(v1.z, d1, a.z); a.w = fmaf(v1.w, d1, a.w);
        a.x = fmaf(v2.x, d2, a.x); a.y = fmaf(v2.y, d2, a.y);
        a.z = fmaf(v2.z, d2, a.z); a.w = fmaf(v2.w, d2, a.w);
        a.x = fmaf(v3.x, d3, a.x); a.y = fmaf(v3.y, d3, a.y);
        a.z = fmaf(v3.z, d3, a.z); a.w = fmaf(v3.w, d3, a.w);
    }
    for (; e < end; e++) {
        int s = g_csrc[e];
        float ds = g_dis[s];
        float4 v = y4[(size_t)s * 32 + lane];
        a.x = fmaf(v.x, ds, a.x); a.y = fmaf(v.y, ds, a.y);
        a.z = fmaf(v.z, ds, a.z); a.w = fmaf(v.w, ds, a.w);
    }
    const float4 b4 = ((const float4*)b)[lane];
    float4 h;
    h.x = fmaxf(fmaf(dn, a.x, b4.x), 0.f);
    h.y = fmaxf(fmaf(dn, a.y, b4.y), 0.f);
    h.z = fmaxf(fmaf(dn, a.z, b4.z), 0.f);
    h.w = fmaxf(fmaf(dn, a.w, b4.w), 0.f);
    ((float4*)g_h)[(size_t)n * 32 + lane] = h;
}

// ---------------------------------------------------------------------------
// K6: decode GEMM via tf32 mma.sync m16n8k8 + softmax.
// 32 nodes/block (two m16 A-tiles), 256 threads (8 warps).
// Warp w owns output cols [w*64, w*64+64) = 8 n-tiles of 8.
__global__ __launch_bounds__(256) void k_dec(float* __restrict__ out) {
    __shared__ __align__(16) float hs[32 * 132];   // row stride 132
    __shared__ float red_m[2][16][8];
    __shared__ float red_s[2][16][8];
    const int tid = threadIdx.x, warp = tid >> 5, lane = tid & 31;
    const int q = lane >> 2, c2 = lane & 3;
    const int n0 = blockIdx.x * 32;

    // load 32 h-rows (128 floats) into hs (g_h is padded past NN; pad rows are 0)
#pragma unroll
    for (int it = 0; it < 4; it++) {
        int idx = it * 256 + tid;          // 0..1023
        int row = idx >> 5, c4 = idx & 31;
        float4 v = *(const float4*)(g_h + (size_t)(n0 + row) * OC + c4 * 4);
        *(float4*)&hs[row * 132 + c4 * 4] = v;
    }
    __syncthreads();

    float c[2][8][4];
#pragma unroll
    for (int t = 0; t < 2; t++)
#pragma unroll
        for (int nt = 0; nt < 8; nt++)
#pragma unroll
            for (int j = 0; j < 4; j++) c[t][nt][j] = 0.f;

    for (int kt = 0; kt < 16; kt++) {
        uint a[2][4];
#pragma unroll
        for (int t = 0; t < 2; t++) {
            int r0 = t * 16 + q;
            a[t][0] = tf32c(hs[r0 * 132 + kt * 8 + c2]);
            a[t][1] = tf32c(hs[(r0 + 8) * 132 + kt * 8 + c2]);
            a[t][2] = tf32c(hs[r0 * 132 + kt * 8 + c2 + 4]);
            a[t][3] = tf32c(hs[(r0 + 8) * 132 + kt * 8 + c2 + 4]);
        }
#pragma unroll
        for (int nt = 0; nt < 8; nt++) {
            uint2 b = g_BpD[(kt * 64 + warp * 8 + nt) * 32 + lane];
#pragma unroll
            for (int t = 0; t < 2; t++) mma_tf32(c[t][nt], a[t], b);
        }
    }

    // --- softmax over 512 cols per row ---
#pragma unroll
    for (int t = 0; t < 2; t++) {
        float mL = -1e30f, mH = -1e30f;
#pragma unroll
        for (int nt = 0; nt < 8; nt++) {
            mL = fmaxf(mL, fmaxf(c[t][nt][0], c[t][nt][1]));
            mH = fmaxf(mH, fmaxf(c[t][nt][2], c[t][nt][3]));
        }
        mL = fmaxf(mL, __shfl_xor_sync(0xffffffffu, mL, 1));
        mL = fmaxf(mL, __shfl_xor_sync(0xffffffffu, mL, 2));
        mH = fmaxf(mH, __shfl_xor_sync(0xffffffffu, mH, 1));
        mH = fmaxf(mH, __shfl_xor_sync(0xffffffffu, mH, 2));
        if (c2 == 0) {
            red_m[t][q][warp] = mL;
            red_m[t][q + 8][warp] = mH;
        }
    }
    __syncthreads();

    float inv[2][2];
#pragma unroll
    for (int t = 0; t < 2; t++) {
        float rmL = red_m[t][q][0], rmH = red_m[t][q + 8][0];
#pragma unroll
        for (int w2 = 1; w2 < 8; w2++) {
            rmL = fmaxf(rmL, red_m[t][q][w2]);
            rmH = fmaxf(rmH, red_m[t][q + 8][w2]);
        }
        float sL = 0.f, sH = 0.f;
#pragma unroll
        for (int nt = 0; nt < 8; nt++) {
            c[t][nt][0] = __expf(c[t][nt][0] - rmL);
            c[t][nt][1] = __expf(c[t][nt][1] - rmL);
            c[t][nt][2] = __expf(c[t][nt][2] - rmH);
            c[t][nt][3] = __expf(c[t][nt][3] - rmH);
            sL += c[t][nt][0] + c[t][nt][1];
            sH += c[t][nt][2] + c[t][nt][3];
        }
        sL += __shfl_xor_sync(0xffffffffu, sL, 1);
        sL += __shfl_xor_sync(0xffffffffu, sL, 2);
        sH += __shfl_xor_sync(0xffffffffu, sH, 1);
        sH += __shfl_xor_sync(0xffffffffu, sH, 2);
        if (c2 == 0) {
            red_s[t][q][warp] = sL;
            red_s[t][q + 8][warp] = sH;
        }
    }
    __syncthreads();

#pragma unroll
    for (int t = 0; t < 2; t++) {
        float sL = 0.f, sH = 0.f;
#pragma unroll
        for (int w2 = 0; w2 < 8; w2++) {
            sL += red_s[t][q][w2];
            sH += red_s[t][q + 8][w2];
        }
        inv[t][0] = 1.f / sL;
        inv[t][1] = 1.f / sH;
    }

#pragma unroll
    for (int t = 0; t < 2; t++) {
        int rowL = n0 + t * 16 + q;
        int rowH = rowL + 8;
#pragma unroll
        for (int nt = 0; nt < 8; nt++) {
            int col = warp * 64 + nt * 8 + 2 * c2;
            if (rowL < NN) {
                float2 v = make_float2(c[t][nt][0] * inv[t][0],
                                       c[t][nt][1] * inv[t][0]);
                *(float2*)&out[(size_t)rowL * IC + col] = v;
            }
            if (rowH < NN) {
                float2 v = make_float2(c[t][nt][2] * inv[t][1],
                                       c[t][nt][3] * inv[t][1]);
                *(float2*)&out[(size_t)rowH * IC + col] = v;
            }
        }
    }
}

// ---------------------------------------------------------------------------
extern "C" void kernel_launch(void* const* d_in, const int* in_sizes, int n_in,
                              void* d_out, int out_size) {
    const float* x    = (const float*)d_in[0];
    const int*   ei   = (const int*)d_in[1];
    const float* Wenc = (const float*)d_in[2];
    const float* benc = (const float*)d_in[3];
    const float* Wdec = (const float*)d_in[4];
    float*       out  = (float*)d_out;

    // Streams/events created once on first (non-capture) call; reused.
    static cudaStream_t sB = nullptr;
    static cudaEvent_t evF = nullptr, evJ = nullptr;
    if (sB == nullptr) {
        cudaStreamCreateWithFlags(&sB, cudaStreamNonBlocking);
        cudaEventCreateWithFlags(&evF, cudaEventDisableTiming);
        cudaEventCreateWithFlags(&evJ, cudaEventDisableTiming);
    }

    // fork: stream B builds the CSR while the main stream runs the encode GEMM
    cudaEventRecord(evF, 0);
    cudaStreamWaitEvent(sB, evF, 0);

    k_zero<<<(NN + 255) / 256, 256, 0, sB>>>();
    k_deg<<<(NE + 255) / 256, 256, 0, sB>>>(ei);
    k_bsum<<<NB, 256, 0, sB>>>();
    k_bscan<<<1, 256, 0, sB>>>();
    k_off<<<NB, 256, 0, sB>>>();
    k_scatter<<<(NE + 255) / 256, 256, 0, sB>>>(ei);

    k_prep<<<128, 256>>>(Wenc, Wdec);
    k_gemm1<<<(NN + 31) / 32, 256>>>(x);

    // join
    cudaEventRecord(evJ, sB);
    cudaStreamWaitEvent(0, evJ, 0);

    k_gather<<<(NN + 7) / 8, 256>>>(benc);
    k_dec<<<(NN + 31) / 32, 256>>>(out);
}

// round 14
// speedup vs baseline: 2.0729x; 1.0106x over previous
#include <cuda_runtime.h>
#include <cuda_bf16.h>

#define NN 50000
#define IC 512
#define OC 128
#define NE 1600000
#define NB 196   // scan blocks: 196*256 = 50176 >= NN

typedef unsigned long long ull;
typedef unsigned int uint;

// ---------------------------------------------------------------------------
// Scratch (static __device__ — no allocation in kernel_launch)
__device__ int   g_deg[NN];
__device__ int   g_off[NN + 1];   // CSR row offsets (by dst)
__device__ int   g_cur[NN];       // scatter cursors
__device__ int   g_csrc[NE];      // CSR column = src node per edge
__device__ float g_dis[NN];
__device__ int   g_bsum[NB];      // per-block degree sums
__device__ int   g_bscan[NB + 1]; // exclusive scan of block sums
__device__ __nv_bfloat16 g_y[(size_t)NN * OC];  // x @ W_enc (UNSCALED, bf16)
__device__ float g_h[(size_t)(NN + 32) * OC];   // relu(dis*(gather) + b), padded

// tf32 B fragments, lane-contiguous:
// enc: [kt(64)][gnt(16)][lane(32)] uint2   (W_enc 512x128)
// dec: [kt(16)][gnt(64)][lane(32)] uint2   (W_dec 128x512)
__device__ uint2 g_BpE[64 * 16 * 32];
__device__ uint2 g_BpD[16 * 64 * 32];

__device__ __forceinline__ uint tf32c(float f) {
    uint u;
    asm("cvt.rna.tf32.f32 %0, %1;" : "=r"(u) : "f"(f));
    return u;
}
__device__ __forceinline__ void mma_tf32(float* c, const uint* a, uint2 b) {
    asm volatile(
        "mma.sync.aligned.m16n8k8.row.col.f32.tf32.tf32.f32 "
        "{%0,%1,%2,%3}, {%4,%5,%6,%7}, {%8,%9}, {%0,%1,%2,%3};"
        : "+f"(c[0]), "+f"(c[1]), "+f"(c[2]), "+f"(c[3])
        : "r"(a[0]), "r"(a[1]), "r"(a[2]), "r"(a[3]), "r"(b.x), "r"(b.y));
}

// ---------------------------------------------------------------------------
// K0: zero deg
__global__ void k_zero() {
    int i = blockIdx.x * blockDim.x + threadIdx.x;
    if (i < NN) g_deg[i] = 0;
}

// K1: dst-degree histogram
__global__ void k_deg(const int* __restrict__ ei) {
    int i = blockIdx.x * blockDim.x + threadIdx.x;
    if (i < NE) atomicAdd(&g_deg[ei[NE + i]], 1);
}

// Scan stage 1: per-block sums of 256 degrees
__global__ __launch_bounds__(256) void k_bsum() {
    __shared__ int ss[8];
    int i = blockIdx.x * 256 + threadIdx.x;
    int v = (i < NN) ? g_deg[i] : 0;
#pragma unroll
    for (int o = 16; o; o >>= 1) v += __shfl_xor_sync(0xffffffffu, v, o);
    if ((threadIdx.x & 31) == 0) ss[threadIdx.x >> 5] = v;
    __syncthreads();
    if (threadIdx.x == 0) {
        int s = 0;
#pragma unroll
        for (int w = 0; w < 8; w++) s += ss[w];
        g_bsum[blockIdx.x] = s;
    }
}

// Scan stage 2: one block exclusive-scans NB block sums
__global__ __launch_bounds__(256) void k_bscan() {
    __shared__ int sc[256];
    int t = threadIdx.x;
    int v = (t < NB) ? g_bsum[t] : 0;
    sc[t] = v;
    __syncthreads();
    for (int off = 1; off < 256; off <<= 1) {
        int u = (t >= off) ? sc[t - off] : 0;
        __syncthreads();
        sc[t] += u;
        __syncthreads();
    }
    if (t < NB) g_bscan[t] = sc[t] - v;   // exclusive
    if (t == NB - 1) g_bscan[NB] = sc[t];
}

// Scan stage 3: per-block scan of degrees + global base -> off/cur/dis
__global__ __launch_bounds__(256) void k_off() {
    __shared__ int sc[256];
    int t = threadIdx.x;
    int i = blockIdx.x * 256 + t;
    int d = (i < NN) ? g_deg[i] : 0;
    sc[t] = d;
    __syncthreads();
    for (int off = 1; off < 256; off <<= 1) {
        int u = (t >= off) ? sc[t - off] : 0;
        __syncthreads();
        sc[t] += u;
        __syncthreads();
    }
    if (i < NN) {
        int base = g_bscan[blockIdx.x] + sc[t] - d;  // exclusive
        g_off[i] = base;
        g_cur[i] = base;
        g_dis[i] = rsqrtf((float)(d + 1));
        if (i == NN - 1) g_off[NN] = base + d;
    }
}

// K3: scatter edges into CSR (order within a row is irrelevant for a sum)
__global__ void k_scatter(const int* __restrict__ ei) {
    int i = blockIdx.x * blockDim.x + threadIdx.x;
    if (i >= NE) return;
    int s = ei[i];
    int d = ei[NE + i];
    int p = atomicAdd(&g_cur[d], 1);
    g_csrc[p] = s;
}

// K_prep: tf32 B fragments for both GEMMs
__global__ void k_prep(const float* __restrict__ We, const float* __restrict__ Wd) {
    int i = blockIdx.x * blockDim.x + threadIdx.x;
    if (i < 64 * 16 * 32) {  // enc fragments
        int kt = i >> 9, gnt = (i >> 5) & 15, lane = i & 31;
        int k = kt * 8 + (lane & 3);
        int n = gnt * 8 + (lane >> 2);
        uint2 b;
        b.x = tf32c(We[k * OC + n]);
        b.y = tf32c(We[(k + 4) * OC + n]);
        g_BpE[i] = b;
    }
    if (i < 16 * 64 * 32) {  // dec fragments
        int kt = i >> 11, gnt = (i >> 5) & 63, lane = i & 31;
        int k = kt * 8 + (lane & 3);
        int n = gnt * 8 + (lane >> 2);
        uint2 b;
        b.x = tf32c(Wd[k * IC + n]);
        b.y = tf32c(Wd[(k + 4) * IC + n]);
        g_BpD[i] = b;
    }
}

// ---------------------------------------------------------------------------
// K4: y = x @ W_enc (UNSCALED, bf16 out) via tf32 mma m16n8k8.
// 32 rows/block (two m16 tiles), 256 threads (8 warps), warp owns 16 cols.
__global__ __launch_bounds__(256) void k_gemm1(const float* __restrict__ x) {
    __shared__ __align__(16) float xs[32 * 132];  // row stride 132
    const int tid = threadIdx.x, warp = tid >> 5, lane = tid & 31;
    const int q = lane >> 2, c2 = lane & 3;
    const int r0blk = blockIdx.x * 32;

    float c[2][2][4];
#pragma unroll
    for (int t = 0; t < 2; t++)
#pragma unroll
        for (int nt = 0; nt < 2; nt++)
#pragma unroll
            for (int j = 0; j < 4; j++) c[t][nt][j] = 0.f;

#pragma unroll 1
    for (int ch = 0; ch < 4; ch++) {
        __syncthreads();
#pragma unroll
        for (int it = 0; it < 4; it++) {
            int idx = it * 256 + tid;
            int row = idx >> 5, c4 = idx & 31;
            int grow = min(r0blk + row, NN - 1);
            float4 v = *(const float4*)(x + (size_t)grow * IC + ch * 128 + c4 * 4);
            *(float4*)&xs[row * 132 + c4 * 4] = v;
        }
        __syncthreads();

#pragma unroll
        for (int kt2 = 0; kt2 < 16; kt2++) {
            int ktg = ch * 16 + kt2;
            uint a[2][4];
#pragma unroll
            for (int t = 0; t < 2; t++) {
                int r = t * 16 + q;
                a[t][0] = tf32c(xs[r * 132 + kt2 * 8 + c2]);
                a[t][1] = tf32c(xs[(r + 8) * 132 + kt2 * 8 + c2]);
                a[t][2] = tf32c(xs[r * 132 + kt2 * 8 + c2 + 4]);
                a[t][3] = tf32c(xs[(r + 8) * 132 + kt2 * 8 + c2 + 4]);
            }
#pragma unroll
            for (int nt = 0; nt < 2; nt++) {
                uint2 b = g_BpE[(ktg * 16 + warp * 2 + nt) * 32 + lane];
#pragma unroll
                for (int t = 0; t < 2; t++) mma_tf32(c[t][nt], a[t], b);
            }
        }
    }

    // write y as bf16 pairs (cols col, col+1 — 4-byte aligned)
#pragma unroll
    for (int t = 0; t < 2; t++) {
        int rowL = r0blk + t * 16 + q;
        int rowH = rowL + 8;
#pragma unroll
        for (int nt = 0; nt < 2; nt++) {
            int col = warp * 16 + nt * 8 + 2 * c2;
            if (rowL < NN)
                *(__nv_bfloat162*)&g_y[(size_t)rowL * OC + col] =
                    __float22bfloat162_rn(make_float2(c[t][nt][0], c[t][nt][1]));
            if (rowH < NN)
                *(__nv_bfloat162*)&g_y[(size_t)rowH * OC + col] =
                    __float22bfloat162_rn(make_float2(c[t][nt][2], c[t][nt][3]));
        }
    }
}

// ---------------------------------------------------------------------------
// K5: gather + epilogue, one warp per node. y rows are bf16 (256 B each);
// lane owns 4 cols as one uint2 (2x bf162). Accumulation in fp32.
// h[n] = relu(dis[n]*(y[n]*dis[n] + sum_{src} y[src]*dis[src]) + b)
__device__ __forceinline__ float4 ld_y4(const uint2* y2, int row, int lane) {
    uint2 u = y2[(size_t)row * 32 + lane];
    float2 lo = __bfloat1622float2(*(__nv_bfloat162*)&u.x);
    float2 hi = __bfloat1622float2(*(__nv_bfloat162*)&u.y);
    return make_float4(lo.x, lo.y, hi.x, hi.y);
}

__global__ __launch_bounds__(256) void k_gather(const float* __restrict__ b) {
    const int w = blockIdx.x * 8 + (threadIdx.x >> 5);
    if (w >= NN) return;
    const int lane = threadIdx.x & 31;
    const int n = w;

    const uint2* __restrict__ y2 = (const uint2*)g_y;  // 32 uint2 per row

    float dn = g_dis[n];
    float4 a = ld_y4(y2, n, lane);  // self loop: y[n] * dis[n]
    a.x *= dn; a.y *= dn; a.z *= dn; a.w *= dn;

    int e = g_off[n], end = g_off[n + 1];
    for (; e + 4 <= end; e += 4) {
        int s0 = g_csrc[e],     s1 = g_csrc[e + 1];
        int s2 = g_csrc[e + 2], s3 = g_csrc[e + 3];
        float d0 = g_dis[s0], d1 = g_dis[s1];
        float d2 = g_dis[s2], d3 = g_dis[s3];
        float4 v0 = ld_y4(y2, s0, lane);
        float4 v1 = ld_y4(y2, s1, lane);
        float4 v2 = ld_y4(y2, s2, lane);
        float4 v3 = ld_y4(y2, s3, lane);
        a.x = fmaf(v0.x, d0, a.x); a.y = fmaf(v0.y, d0, a.y);
        a.z = fmaf(v0.z, d0, a.z); a.w = fmaf(v0.w, d0, a.w);
        a.x = fmaf(v1.x, d1, a.x); a.y = fmaf(v1.y, d1, a.y);
        a.z = fmaf(v1.z, d1, a.z); a.w = fmaf(v1.w, d1, a.w);
        a.x = fmaf(v2.x, d2, a.x); a.y = fmaf(v2.y, d2, a.y);
        a.z = fmaf(v2.z, d2, a.z); a.w = fmaf(v2.w, d2, a.w);
        a.x = fmaf(v3.x, d3, a.x); a.y = fmaf(v3.y, d3, a.y);
        a.z = fmaf(v3.z, d3, a.z); a.w = fmaf(v3.w, d3, a.w);
    }
    for (; e < end; e++) {
        int s = g_csrc[e];
        float ds = g_dis[s];
        float4 v = ld_y4(y2, s, lane);
        a.x = fmaf(v.x, ds, a.x); a.y = fmaf(v.y, ds, a.y);
        a.z = fmaf(v.z, ds, a.z); a.w = fmaf(v.w, ds, a.w);
    }
    const float4 b4 = ((const float4*)b)[lane];
    float4 h;
    h.x = fmaxf(fmaf(dn, a.x, b4.x), 0.f);
    h.y = fmaxf(fmaf(dn, a.y, b4.y), 0.f);
    h.z = fmaxf(fmaf(dn, a.z, b4.z), 0.f);
    h.w = fmaxf(fmaf(dn, a.w, b4.w), 0.f);
    ((float4*)g_h)[(size_t)n * 32 + lane] = h;
}

// ---------------------------------------------------------------------------
// K6: decode GEMM via tf32 mma.sync m16n8k8 + softmax.
// 32 nodes/block (two m16 A-tiles), 256 threads (8 warps).
__global__ __launch_bounds__(256) void k_dec(float* __restrict__ out) {
    __shared__ __align__(16) float hs[32 * 132];   // row stride 132
    __shared__ float red_m[2][16][8];
    __shared__ float red_s[2][16][8];
    const int tid = threadIdx.x, warp = tid >> 5, lane = tid & 31;
    const int q = lane >> 2, c2 = lane & 3;
    const int n0 = blockIdx.x * 32;

#pragma unroll
    for (int it = 0; it < 4; it++) {
        int idx = it * 256 + tid;
        int row = idx >> 5, c4 = idx & 31;
        float4 v = *(const float4*)(g_h + (size_t)(n0 + row) * OC + c4 * 4);
        *(float4*)&hs[row * 132 + c4 * 4] = v;
    }
    __syncthreads();

    float c[2][8][4];
#pragma unroll
    for (int t = 0; t < 2; t++)
#pragma unroll
        for (int nt = 0; nt < 8; nt++)
#pragma unroll
            for (int j = 0; j < 4; j++) c[t][nt][j] = 0.f;

    for (int kt = 0; kt < 16; kt++) {
        uint a[2][4];
#pragma unroll
        for (int t = 0; t < 2; t++) {
            int r0 = t * 16 + q;
            a[t][0] = tf32c(hs[r0 * 132 + kt * 8 + c2]);
            a[t][1] = tf32c(hs[(r0 + 8) * 132 + kt * 8 + c2]);
            a[t][2] = tf32c(hs[r0 * 132 + kt * 8 + c2 + 4]);
            a[t][3] = tf32c(hs[(r0 + 8) * 132 + kt * 8 + c2 + 4]);
        }
#pragma unroll
        for (int nt = 0; nt < 8; nt++) {
            uint2 b = g_BpD[(kt * 64 + warp * 8 + nt) * 32 + lane];
#pragma unroll
            for (int t = 0; t < 2; t++) mma_tf32(c[t][nt], a[t], b);
        }
    }

    // --- softmax over 512 cols per row ---
#pragma unroll
    for (int t = 0; t < 2; t++) {
        float mL = -1e30f, mH = -1e30f;
#pragma unroll
        for (int nt = 0; nt < 8; nt++) {
            mL = fmaxf(mL, fmaxf(c[t][nt][0], c[t][nt][1]));
            mH = fmaxf(mH, fmaxf(c[t][nt][2], c[t][nt][3]));
        }
        mL = fmaxf(mL, __shfl_xor_sync(0xffffffffu, mL, 1));
        mL = fmaxf(mL, __shfl_xor_sync(0xffffffffu, mL, 2));
        mH = fmaxf(mH, __shfl_xor_sync(0xffffffffu, mH, 1));
        mH = fmaxf(mH, __shfl_xor_sync(0xffffffffu, mH, 2));
        if (c2 == 0) {
            red_m[t][q][warp] = mL;
            red_m[t][q + 8][warp] = mH;
        }
    }
    __syncthreads();

    float inv[2][2];
#pragma unroll
    for (int t = 0; t < 2; t++) {
        float rmL = red_m[t][q][0], rmH = red_m[t][q + 8][0];
#pragma unroll
        for (int w2 = 1; w2 < 8; w2++) {
            rmL = fmaxf(rmL, red_m[t][q][w2]);
            rmH = fmaxf(rmH, red_m[t][q + 8][w2]);
        }
        float sL = 0.f, sH = 0.f;
#pragma unroll
        for (int nt = 0; nt < 8; nt++) {
            c[t][nt][0] = __expf(c[t][nt][0] - rmL);
            c[t][nt][1] = __expf(c[t][nt][1] - rmL);
            c[t][nt][2] = __expf(c[t][nt][2] - rmH);
            c[t][nt][3] = __expf(c[t][nt][3] - rmH);
            sL += c[t][nt][0] + c[t][nt][1];
            sH += c[t][nt][2] + c[t][nt][3];
        }
        sL += __shfl_xor_sync(0xffffffffu, sL, 1);
        sL += __shfl_xor_sync(0xffffffffu, sL, 2);
        sH += __shfl_xor_sync(0xffffffffu, sH, 1);
        sH += __shfl_xor_sync(0xffffffffu, sH, 2);
        if (c2 == 0) {
            red_s[t][q][warp] = sL;
            red_s[t][q + 8][warp] = sH;
        }
    }
    __syncthreads();

#pragma unroll
    for (int t = 0; t < 2; t++) {
        float sL = 0.f, sH = 0.f;
#pragma unroll
        for (int w2 = 0; w2 < 8; w2++) {
            sL += red_s[t][q][w2];
            sH += red_s[t][q + 8][w2];
        }
        inv[t][0] = 1.f / sL;
        inv[t][1] = 1.f / sH;
    }

#pragma unroll
    for (int t = 0; t < 2; t++) {
        int rowL = n0 + t * 16 + q;
        int rowH = rowL + 8;
#pragma unroll
        for (int nt = 0; nt < 8; nt++) {
            int col = warp * 64 + nt * 8 + 2 * c2;
            if (rowL < NN) {
                float2 v = make_float2(c[t][nt][0] * inv[t][0],
                                       c[t][nt][1] * inv[t][0]);
                *(float2*)&out[(size_t)rowL * IC + col] = v;
            }
            if (rowH < NN) {
                float2 v = make_float2(c[t][nt][2] * inv[t][1],
                                       c[t][nt][3] * inv[t][1]);
                *(float2*)&out[(size_t)rowH * IC + col] = v;
            }
        }
    }
}

// ---------------------------------------------------------------------------
extern "C" void kernel_launch(void* const* d_in, const int* in_sizes, int n_in,
                              void* d_out, int out_size) {
    const float* x    = (const float*)d_in[0];
    const int*   ei   = (const int*)d_in[1];
    const float* Wenc = (const float*)d_in[2];
    const float* benc = (const float*)d_in[3];
    const float* Wdec = (const float*)d_in[4];
    float*       out  = (float*)d_out;

    // Streams/events created once on first (non-capture) call; reused.
    static cudaStream_t sB = nullptr;
    static cudaEvent_t evF = nullptr, evJ = nullptr;
    if (sB == nullptr) {
        cudaStreamCreateWithFlags(&sB, cudaStreamNonBlocking);
        cudaEventCreateWithFlags(&evF, cudaEventDisableTiming);
        cudaEventCreateWithFlags(&evJ, cudaEventDisableTiming);
    }

    // fork: stream B builds the CSR while the main stream runs the encode GEMM
    cudaEventRecord(evF, 0);
    cudaStreamWaitEvent(sB, evF, 0);

    k_zero<<<(NN + 255) / 256, 256, 0, sB>>>();
    k_deg<<<(NE + 255) / 256, 256, 0, sB>>>(ei);
    k_bsum<<<NB, 256, 0, sB>>>();
    k_bscan<<<1, 256, 0, sB>>>();
    k_off<<<NB, 256, 0, sB>>>();
    k_scatter<<<(NE + 255) / 256, 256, 0, sB>>>(ei);

    k_prep<<<128, 256>>>(Wenc, Wdec);
    k_gemm1<<<(NN + 31) / 32, 256>>>(x);

    // join
    cudaEventRecord(evJ, sB);
    cudaStreamWaitEvent(0, evJ, 0);

    k_gather<<<(NN + 7) / 8, 256>>>(benc);
    k_dec<<<(NN + 31) / 32, 256>>>(out);
}

// round 15
// speedup vs baseline: 2.1084x; 1.0171x over previous
#include <cuda_runtime.h>
#include <cuda_bf16.h>

#define NN 50000
#define IC 512
#define OC 128
#define NE 1600000
#define NB 196   // scan blocks: 196*256 = 50176 >= NN

typedef unsigned long long ull;
typedef unsigned int uint;

// ---------------------------------------------------------------------------
// Scratch (static __device__ — zero-initialized at load; no allocation)
__device__ int   g_deg[NN];       // zeroed at start of each call's lifecycle
__device__ int   g_off[NN + 1];   // CSR row offsets (by dst)
__device__ int   g_cur[NN];       // scatter cursors
__device__ int   g_csrc[NE];      // CSR column = src node per edge
__device__ float g_dis[NN];
__device__ int   g_bsum[NB];      // per-block degree sums
__device__ __nv_bfloat16 g_y[(size_t)NN * OC];  // x @ W_enc (UNSCALED, bf16)
__device__ float g_h[(size_t)(NN + 32) * OC];   // relu(dis*(gather) + b), padded

// tf32 B fragments, lane-contiguous:
__device__ uint2 g_BpE[64 * 16 * 32];
__device__ uint2 g_BpD[16 * 64 * 32];

__device__ __forceinline__ uint tf32c(float f) {
    uint u;
    asm("cvt.rna.tf32.f32 %0, %1;" : "=r"(u) : "f"(f));
    return u;
}
__device__ __forceinline__ void mma_tf32(float* c, const uint* a, uint2 b) {
    asm volatile(
        "mma.sync.aligned.m16n8k8.row.col.f32.tf32.tf32.f32 "
        "{%0,%1,%2,%3}, {%4,%5,%6,%7}, {%8,%9}, {%0,%1,%2,%3};"
        : "+f"(c[0]), "+f"(c[1]), "+f"(c[2]), "+f"(c[3])
        : "r"(a[0]), "r"(a[1]), "r"(a[2]), "r"(a[3]), "r"(b.x), "r"(b.y));
}

// ---------------------------------------------------------------------------
// K1: dst-degree histogram (g_deg is zero on entry: static init on first call,
// re-zeroed by k_off on every call)
__global__ void k_deg(const int* __restrict__ ei) {
    int i = blockIdx.x * blockDim.x + threadIdx.x;
    if (i < NE) atomicAdd(&g_deg[ei[NE + i]], 1);
}

// Scan stage 1: per-block sums of 256 degrees
__global__ __launch_bounds__(256) void k_bsum() {
    __shared__ int ss[8];
    int i = blockIdx.x * 256 + threadIdx.x;
    int v = (i < NN) ? g_deg[i] : 0;
#pragma unroll
    for (int o = 16; o; o >>= 1) v += __shfl_xor_sync(0xffffffffu, v, o);
    if ((threadIdx.x & 31) == 0) ss[threadIdx.x >> 5] = v;
    __syncthreads();
    if (threadIdx.x == 0) {
        int s = 0;
#pragma unroll
        for (int w = 0; w < 8; w++) s += ss[w];
        g_bsum[blockIdx.x] = s;
    }
}

// Scan stage 2 (fused): per-block redundant reduce of bsum below bid +
// per-block scan of degrees -> off/cur/dis. Also re-zeros g_deg for next call.
__global__ __launch_bounds__(256) void k_off() {
    __shared__ int sc[256];
    __shared__ int sbase[8];
    const int t = threadIdx.x;
    const int bid = blockIdx.x;
    const int i = bid * 256 + t;

    // block-level exclusive base = sum of bsum[j], j < bid
    int v = (t < bid && t < NB) ? g_bsum[t] : 0;
#pragma unroll
    for (int o = 16; o; o >>= 1) v += __shfl_xor_sync(0xffffffffu, v, o);
    if ((t & 31) == 0) sbase[t >> 5] = v;
    __syncthreads();
    int gbase = 0;
#pragma unroll
    for (int w = 0; w < 8; w++) gbase += sbase[w];

    int d = (i < NN) ? g_deg[i] : 0;
    sc[t] = d;
    __syncthreads();
    for (int off = 1; off < 256; off <<= 1) {
        int u = (t >= off) ? sc[t - off] : 0;
        __syncthreads();
        sc[t] += u;
        __syncthreads();
    }
    if (i < NN) {
        int base = gbase + sc[t] - d;  // exclusive
        g_off[i] = base;
        g_cur[i] = base;
        g_dis[i] = rsqrtf((float)(d + 1));
        g_deg[i] = 0;                  // ready for next call
        if (i == NN - 1) g_off[NN] = base + d;
    }
}

// K3: scatter edges into CSR (order within a row is irrelevant for a sum)
__global__ void k_scatter(const int* __restrict__ ei) {
    int i = blockIdx.x * blockDim.x + threadIdx.x;
    if (i >= NE) return;
    int s = ei[i];
    int d = ei[NE + i];
    int p = atomicAdd(&g_cur[d], 1);
    g_csrc[p] = s;
}

// K_prep: tf32 B fragments for both GEMMs
__global__ void k_prep(const float* __restrict__ We, const float* __restrict__ Wd) {
    int i = blockIdx.x * blockDim.x + threadIdx.x;
    if (i < 64 * 16 * 32) {  // enc fragments
        int kt = i >> 9, gnt = (i >> 5) & 15, lane = i & 31;
        int k = kt * 8 + (lane & 3);
        int n = gnt * 8 + (lane >> 2);
        uint2 b;
        b.x = tf32c(We[k * OC + n]);
        b.y = tf32c(We[(k + 4) * OC + n]);
        g_BpE[i] = b;
    }
    if (i < 16 * 64 * 32) {  // dec fragments
        int kt = i >> 11, gnt = (i >> 5) & 63, lane = i & 31;
        int k = kt * 8 + (lane & 3);
        int n = gnt * 8 + (lane >> 2);
        uint2 b;
        b.x = tf32c(Wd[k * IC + n]);
        b.y = tf32c(Wd[(k + 4) * IC + n]);
        g_BpD[i] = b;
    }
}

// ---------------------------------------------------------------------------
// K4: y = x @ W_enc (UNSCALED, bf16 out) via tf32 mma m16n8k8.
__global__ __launch_bounds__(256) void k_gemm1(const float* __restrict__ x) {
    __shared__ __align__(16) float xs[32 * 132];  // row stride 132
    const int tid = threadIdx.x, warp = tid >> 5, lane = tid & 31;
    const int q = lane >> 2, c2 = lane & 3;
    const int r0blk = blockIdx.x * 32;

    float c[2][2][4];
#pragma unroll
    for (int t = 0; t < 2; t++)
#pragma unroll
        for (int nt = 0; nt < 2; nt++)
#pragma unroll
            for (int j = 0; j < 4; j++) c[t][nt][j] = 0.f;

#pragma unroll 1
    for (int ch = 0; ch < 4; ch++) {
        __syncthreads();
#pragma unroll
        for (int it = 0; it < 4; it++) {
            int idx = it * 256 + tid;
            int row = idx >> 5, c4 = idx & 31;
            int grow = min(r0blk + row, NN - 1);
            float4 v = *(const float4*)(x + (size_t)grow * IC + ch * 128 + c4 * 4);
            *(float4*)&xs[row * 132 + c4 * 4] = v;
        }
        __syncthreads();

#pragma unroll
        for (int kt2 = 0; kt2 < 16; kt2++) {
            int ktg = ch * 16 + kt2;
            uint a[2][4];
#pragma unroll
            for (int t = 0; t < 2; t++) {
                int r = t * 16 + q;
                a[t][0] = tf32c(xs[r * 132 + kt2 * 8 + c2]);
                a[t][1] = tf32c(xs[(r + 8) * 132 + kt2 * 8 + c2]);
                a[t][2] = tf32c(xs[r * 132 + kt2 * 8 + c2 + 4]);
                a[t][3] = tf32c(xs[(r + 8) * 132 + kt2 * 8 + c2 + 4]);
            }
#pragma unroll
            for (int nt = 0; nt < 2; nt++) {
                uint2 b = g_BpE[(ktg * 16 + warp * 2 + nt) * 32 + lane];
#pragma unroll
                for (int t = 0; t < 2; t++) mma_tf32(c[t][nt], a[t], b);
            }
        }
    }

#pragma unroll
    for (int t = 0; t < 2; t++) {
        int rowL = r0blk + t * 16 + q;
        int rowH = rowL + 8;
#pragma unroll
        for (int nt = 0; nt < 2; nt++) {
            int col = warp * 16 + nt * 8 + 2 * c2;
            if (rowL < NN)
                *(__nv_bfloat162*)&g_y[(size_t)rowL * OC + col] =
                    __float22bfloat162_rn(make_float2(c[t][nt][0], c[t][nt][1]));
            if (rowH < NN)
                *(__nv_bfloat162*)&g_y[(size_t)rowH * OC + col] =
                    __float22bfloat162_rn(make_float2(c[t][nt][2], c[t][nt][3]));
        }
    }
}

// ---------------------------------------------------------------------------
// K5: gather + epilogue, one warp per node, 8-wide software pipeline (MLP 8).
__device__ __forceinline__ float4 ld_y4(const uint2* y2, int row, int lane) {
    uint2 u = y2[(size_t)row * 32 + lane];
    float2 lo = __bfloat1622float2(*(__nv_bfloat162*)&u.x);
    float2 hi = __bfloat1622float2(*(__nv_bfloat162*)&u.y);
    return make_float4(lo.x, lo.y, hi.x, hi.y);
}

__global__ __launch_bounds__(256) void k_gather(const float* __restrict__ b) {
    const int w = blockIdx.x * 8 + (threadIdx.x >> 5);
    if (w >= NN) return;
    const int lane = threadIdx.x & 31;
    const int n = w;

    const uint2* __restrict__ y2 = (const uint2*)g_y;

    float dn = g_dis[n];
    float4 a = ld_y4(y2, n, lane);  // self loop
    a.x *= dn; a.y *= dn; a.z *= dn; a.w *= dn;

    int e = g_off[n], end = g_off[n + 1];
    for (; e + 8 <= end; e += 8) {
        int s[8];
#pragma unroll
        for (int j = 0; j < 8; j++) s[j] = g_csrc[e + j];
        float4 v[8];
#pragma unroll
        for (int j = 0; j < 8; j++) v[j] = ld_y4(y2, s[j], lane);
        float ds[8];
#pragma unroll
        for (int j = 0; j < 8; j++) ds[j] = g_dis[s[j]];
#pragma unroll
        for (int j = 0; j < 8; j++) {
            a.x = fmaf(v[j].x, ds[j], a.x);
            a.y = fmaf(v[j].y, ds[j], a.y);
            a.z = fmaf(v[j].z, ds[j], a.z);
            a.w = fmaf(v[j].w, ds[j], a.w);
        }
    }
    for (; e < end; e++) {
        int s = g_csrc[e];
        float ds = g_dis[s];
        float4 v = ld_y4(y2, s, lane);
        a.x = fmaf(v.x, ds, a.x); a.y = fmaf(v.y, ds, a.y);
        a.z = fmaf(v.z, ds, a.z); a.w = fmaf(v.w, ds, a.w);
    }
    const float4 b4 = ((const float4*)b)[lane];
    float4 h;
    h.x = fmaxf(fmaf(dn, a.x, b4.x), 0.f);
    h.y = fmaxf(fmaf(dn, a.y, b4.y), 0.f);
    h.z = fmaxf(fmaf(dn, a.z, b4.z), 0.f);
    h.w = fmaxf(fmaf(dn, a.w, b4.w), 0.f);
    ((float4*)g_h)[(size_t)n * 32 + lane] = h;
}

// ---------------------------------------------------------------------------
// K6: decode GEMM via tf32 mma.sync m16n8k8 + softmax.
__global__ __launch_bounds__(256) void k_dec(float* __restrict__ out) {
    __shared__ __align__(16) float hs[32 * 132];
    __shared__ float red_m[2][16][8];
    __shared__ float red_s[2][16][8];
    const int tid = threadIdx.x, warp = tid >> 5, lane = tid & 31;
    const int q = lane >> 2, c2 = lane & 3;
    const int n0 = blockIdx.x * 32;

#pragma unroll
    for (int it = 0; it < 4; it++) {
        int idx = it * 256 + tid;
        int row = idx >> 5, c4 = idx & 31;
        float4 v = *(const float4*)(g_h + (size_t)(n0 + row) * OC + c4 * 4);
        *(float4*)&hs[row * 132 + c4 * 4] = v;
    }
    __syncthreads();

    float c[2][8][4];
#pragma unroll
    for (int t = 0; t < 2; t++)
#pragma unroll
        for (int nt = 0; nt < 8; nt++)
#pragma unroll
            for (int j = 0; j < 4; j++) c[t][nt][j] = 0.f;

    for (int kt = 0; kt < 16; kt++) {
        uint a[2][4];
#pragma unroll
        for (int t = 0; t < 2; t++) {
            int r0 = t * 16 + q;
            a[t][0] = tf32c(hs[r0 * 132 + kt * 8 + c2]);
            a[t][1] = tf32c(hs[(r0 + 8) * 132 + kt * 8 + c2]);
            a[t][2] = tf32c(hs[r0 * 132 + kt * 8 + c2 + 4]);
            a[t][3] = tf32c(hs[(r0 + 8) * 132 + kt * 8 + c2 + 4]);
        }
#pragma unroll
        for (int nt = 0; nt < 8; nt++) {
            uint2 b = g_BpD[(kt * 64 + warp * 8 + nt) * 32 + lane];
#pragma unroll
            for (int t = 0; t < 2; t++) mma_tf32(c[t][nt], a[t], b);
        }
    }

    // --- softmax over 512 cols per row ---
#pragma unroll
    for (int t = 0; t < 2; t++) {
        float mL = -1e30f, mH = -1e30f;
#pragma unroll
        for (int nt = 0; nt < 8; nt++) {
            mL = fmaxf(mL, fmaxf(c[t][nt][0], c[t][nt][1]));
            mH = fmaxf(mH, fmaxf(c[t][nt][2], c[t][nt][3]));
        }
        mL = fmaxf(mL, __shfl_xor_sync(0xffffffffu, mL, 1));
        mL = fmaxf(mL, __shfl_xor_sync(0xffffffffu, mL, 2));
        mH = fmaxf(mH, __shfl_xor_sync(0xffffffffu, mH, 1));
        mH = fmaxf(mH, __shfl_xor_sync(0xffffffffu, mH, 2));
        if (c2 == 0) {
            red_m[t][q][warp] = mL;
            red_m[t][q + 8][warp] = mH;
        }
    }
    __syncthreads();

    float inv[2][2];
#pragma unroll
    for (int t = 0; t < 2; t++) {
        float rmL = red_m[t][q][0], rmH = red_m[t][q + 8][0];
#pragma unroll
        for (int w2 = 1; w2 < 8; w2++) {
            rmL = fmaxf(rmL, red_m[t][q][w2]);
            rmH = fmaxf(rmH, red_m[t][q + 8][w2]);
        }
        float sL = 0.f, sH = 0.f;
#pragma unroll
        for (int nt = 0; nt < 8; nt++) {
            c[t][nt][0] = __expf(c[t][nt][0] - rmL);
            c[t][nt][1] = __expf(c[t][nt][1] - rmL);
            c[t][nt][2] = __expf(c[t][nt][2] - rmH);
            c[t][nt][3] = __expf(c[t][nt][3] - rmH);
            sL += c[t][nt][0] + c[t][nt][1];
            sH += c[t][nt][2] + c[t][nt][3];
        }
        sL += __shfl_xor_sync(0xffffffffu, sL, 1);
        sL += __shfl_xor_sync(0xffffffffu, sL, 2);
        sH += __shfl_xor_sync(0xffffffffu, sH, 1);
        sH += __shfl_xor_sync(0xffffffffu, sH, 2);
        if (c2 == 0) {
            red_s[t][q][warp] = sL;
            red_s[t][q + 8][warp] = sH;
        }
    }
    __syncthreads();

#pragma unroll
    for (int t = 0; t < 2; t++) {
        float sL = 0.f, sH = 0.f;
#pragma unroll
        for (int w2 = 0; w2 < 8; w2++) {
            sL += red_s[t][q][w2];
            sH += red_s[t][q + 8][w2];
        }
        inv[t][0] = 1.f / sL;
        inv[t][1] = 1.f / sH;
    }

#pragma unroll
    for (int t = 0; t < 2; t++) {
        int rowL = n0 + t * 16 + q;
        int rowH = rowL + 8;
#pragma unroll
        for (int nt = 0; nt < 8; nt++) {
            int col = warp * 64 + nt * 8 + 2 * c2;
            if (rowL < NN) {
                float2 v = make_float2(c[t][nt][0] * inv[t][0],
                                       c[t][nt][1] * inv[t][0]);
                *(float2*)&out[(size_t)rowL * IC + col] = v;
            }
            if (rowH < NN) {
                float2 v = make_float2(c[t][nt][2] * inv[t][1],
                                       c[t][nt][3] * inv[t][1]);
                *(float2*)&out[(size_t)rowH * IC + col] = v;
            }
        }
    }
}

// ---------------------------------------------------------------------------
extern "C" void kernel_launch(void* const* d_in, const int* in_sizes, int n_in,
                              void* d_out, int out_size) {
    const float* x    = (const float*)d_in[0];
    const int*   ei   = (const int*)d_in[1];
    const float* Wenc = (const float*)d_in[2];
    const float* benc = (const float*)d_in[3];
    const float* Wdec = (const float*)d_in[4];
    float*       out  = (float*)d_out;

    // Streams/events created once on first (non-capture) call; reused.
    static cudaStream_t sB = nullptr;
    static cudaEvent_t evF = nullptr, evJ = nullptr;
    if (sB == nullptr) {
        cudaStreamCreateWithFlags(&sB, cudaStreamNonBlocking);
        cudaEventCreateWithFlags(&evF, cudaEventDisableTiming);
        cudaEventCreateWithFlags(&evJ, cudaEventDisableTiming);
    }

    // fork: stream B builds the CSR while the main stream runs the encode GEMM
    cudaEventRecord(evF, 0);
    cudaStreamWaitEvent(sB, evF, 0);

    k_deg<<<(NE + 255) / 256, 256, 0, sB>>>(ei);
    k_bsum<<<NB, 256, 0, sB>>>();
    k_off<<<NB, 256, 0, sB>>>();
    k_scatter<<<(NE + 255) / 256, 256, 0, sB>>>(ei);

    k_prep<<<128, 256>>>(Wenc, Wdec);
    k_gemm1<<<(NN + 31) / 32, 256>>>(x);

    // join
    cudaEventRecord(evJ, sB);
    cudaStreamWaitEvent(0, evJ, 0);

    k_gather<<<(NN + 7) / 8, 256>>>(benc);
    k_dec<<<(NN + 31) / 32, 256>>>(out);
}